// round 10
// baseline (speedup 1.0000x reference)
#include <cuda_runtime.h>

// Fixed shapes
#define Q     32
#define NCLS  4
#define NVAL  16
#define NSAMP 256          // bs*seq = 8*32
#define NWORK 32768        // total thread work items (NSAMP*Q*NVAL/4)
// weights
#define W_CLASS 1.0f
#define W_BBOX  5.0f
#define W_GIOU  2.0f

struct PredXY { float x0, y0, x1, y1, area; };

// Register-resident class select: 2-level SELP tree, no local memory.
__device__ __forceinline__ float sel_logit(const float4& lg, int id)
{
    const float lo = (id & 1) ? lg.y : lg.x;
    const float hi = (id & 1) ? lg.w : lg.z;
    return (id & 2) ? hi : lo;
}

__device__ __forceinline__ float pair_cost(const PredXY& pp, const float4& p,
                                           const float4& t, float cls)
{
    // L1 in cxcywh space
    const float l1 = fabsf(p.x - t.x) + fabsf(p.y - t.y)
                   + fabsf(p.z - t.z) + fabsf(p.w - t.w);

    const float tx0 = t.x - 0.5f * t.z, ty0 = t.y - 0.5f * t.w;
    const float tx1 = t.x + 0.5f * t.z, ty1 = t.y + 0.5f * t.w;
    const float area_t = (tx1 - tx0) * (ty1 - ty0);

    const float iw = fmaxf(fminf(pp.x1, tx1) - fmaxf(pp.x0, tx0), 0.0f);
    const float ih = fmaxf(fminf(pp.y1, ty1) - fmaxf(pp.y0, ty0), 0.0f);
    const float inter = iw * ih;
    const float uni   = pp.area + area_t - inter;

    const float ew = fmaxf(fmaxf(pp.x1, tx1) - fminf(pp.x0, tx0), 0.0f);
    const float eh = fmaxf(fmaxf(pp.y1, ty1) - fminf(pp.y0, ty0), 0.0f);
    const float area_e = ew * eh;

    // giou = iou - 1 + uni/area_e : both fast divides independent,
    // so the two MUFU.RCPs issue back-to-back.
    const float iou  = __fdividef(inter, uni);
    const float giou = (iou - 1.0f) + __fdividef(uni, area_e);

    return W_BBOX * l1 - W_CLASS * cls - W_GIOU * giou;
}

// Thread -> (sample i, query a, 4 consecutive targets). 32768 work items on
// 148 CTAs x 224 threads = 33152 slots: exactly ONE CTA per SM (perfect
// balance, full-chip spread), bounds-guarded tail. No smem, no barriers,
// MLP=7 front-batched loads, one STG.128 per thread.
//
// Index algebra: gtid = 128*i + 4*a + bq, so
//   pred/logit index  i*Q + a   == gtid >> 2
//   ids index         i*8 + bq  == ((gtid>>7)<<3) | (gtid&3)
//   tgt base          i*Q + 4bq == ((gtid>>7)<<5) | ((gtid&3)<<2)
__global__ __launch_bounds__(224)
void matcher_kernel(const float4* __restrict__ pred_logits,  // [256*Q] (NCLS=4)
                    const float4* __restrict__ pred_boxes,   // [256*Q]
                    const float4* __restrict__ tgt_boxes,    // [256*Q]
                    const int4*   __restrict__ hand_type,    // [256*Q/4]
                    float4*       __restrict__ out)          // [NWORK]
{
    const int gtid = blockIdx.x * 224 + threadIdx.x;
    if (gtid >= NWORK) return;

    const int pa = gtid >> 2;                          // i*Q + a
    const int ih = gtid >> 7;                          // sample i
    const int bq = gtid & 3;                           // target quad
    const int ib = (ih << 3) | bq;                     // ids index
    const int tb = (ih << 5) | (bq << 2);              // tgt base

    const float4 p   = __ldg(&pred_boxes [pa]);
    const float4 lg  = __ldg(&pred_logits[pa]);
    const int4   ids = __ldg(&hand_type  [ib]);
    const float4 t0 = __ldg(&tgt_boxes[tb + 0]);
    const float4 t1 = __ldg(&tgt_boxes[tb + 1]);
    const float4 t2 = __ldg(&tgt_boxes[tb + 2]);
    const float4 t3 = __ldg(&tgt_boxes[tb + 3]);

    PredXY pp;
    pp.x0 = p.x - 0.5f * p.z;  pp.y0 = p.y - 0.5f * p.w;
    pp.x1 = p.x + 0.5f * p.z;  pp.y1 = p.y + 0.5f * p.w;
    pp.area = (pp.x1 - pp.x0) * (pp.y1 - pp.y0);

    float4 r;
    r.x = pair_cost(pp, p, t0, sel_logit(lg, ids.x));
    r.y = pair_cost(pp, p, t1, sel_logit(lg, ids.y));
    r.z = pair_cost(pp, p, t2, sel_logit(lg, ids.z));
    r.w = pair_cost(pp, p, t3, sel_logit(lg, ids.w));

    out[gtid] = r;
}

extern "C" void kernel_launch(void* const* d_in, const int* in_sizes, int n_in,
                              void* d_out, int out_size)
{
    const float4* pred_logits = (const float4*)d_in[0];
    const float4* pred_boxes  = (const float4*)d_in[1];
    const float4* tgt_boxes   = (const float4*)d_in[2];
    const int4*   hand_type   = (const int4*)d_in[3];
    (void)in_sizes; (void)n_in; (void)out_size;

    matcher_kernel<<<148, 224>>>(pred_logits, pred_boxes, tgt_boxes,
                                 hand_type, (float4*)d_out);
}

// round 11
// speedup vs baseline: 1.1840x; 1.1840x over previous
#include <cuda_runtime.h>

// Fixed shapes
#define Q     32
#define NCLS  4
#define NVAL  16
#define NSAMP 256          // bs*seq = 8*32
// weights
#define W_CLASS 1.0f
#define W_BBOX  5.0f
#define W_GIOU  2.0f

struct PredXY { float x0, y0, x1, y1, area; };

// Register-resident class select: 2-level SELP tree, no local memory.
__device__ __forceinline__ float sel_logit(const float4& lg, int id)
{
    const float lo = (id & 1) ? lg.y : lg.x;
    const float hi = (id & 1) ? lg.w : lg.z;
    return (id & 2) ? hi : lo;
}

__device__ __forceinline__ float pair_cost(const PredXY& pp, const float4& p,
                                           const float4& t, float cls)
{
    // L1 in cxcywh space
    const float l1 = fabsf(p.x - t.x) + fabsf(p.y - t.y)
                   + fabsf(p.z - t.z) + fabsf(p.w - t.w);

    const float tx0 = t.x - 0.5f * t.z, ty0 = t.y - 0.5f * t.w;
    const float tx1 = t.x + 0.5f * t.z, ty1 = t.y + 0.5f * t.w;
    const float area_t = (tx1 - tx0) * (ty1 - ty0);

    const float iw = fmaxf(fminf(pp.x1, tx1) - fmaxf(pp.x0, tx0), 0.0f);
    const float ih = fmaxf(fminf(pp.y1, ty1) - fmaxf(pp.y0, ty0), 0.0f);
    const float inter = iw * ih;
    const float uni   = pp.area + area_t - inter;

    const float ew = fmaxf(fmaxf(pp.x1, tx1) - fminf(pp.x0, tx0), 0.0f);
    const float eh = fmaxf(fmaxf(pp.y1, ty1) - fminf(pp.y0, ty0), 0.0f);
    const float area_e = ew * eh;

    // giou = iou - 1 + uni/area_e : both fast divides independent,
    // so the two MUFU.RCPs issue back-to-back.
    const float iou  = __fdividef(inter, uni);
    const float giou = (iou - 1.0f) + __fdividef(uni, area_e);

    return W_BBOX * l1 - W_CLASS * cls - W_GIOU * giou;
}

// Thread -> (sample i, query a, 4 consecutive targets). 32768 threads as
// 128 CTAs x 256 threads — the measured-optimal shape across the full
// lattice {256x512, 256x128, 128x256, 64x512, 128x64, 148x224}; reproduced
// twice at 4.54/4.61us. No smem, no barriers, MLP=7 front-batched loads,
// one STG.128 per thread.
//
// Index algebra: gtid = 128*i + 4*a + bq, so
//   pred/logit index  i*Q + a   == gtid >> 2
//   ids index         i*8 + bq  == ((gtid>>7)<<3) | (gtid&3)
//   tgt base          i*Q + 4bq == ((gtid>>7)<<5) | ((gtid&3)<<2)
__global__ __launch_bounds__(256)
void matcher_kernel(const float4* __restrict__ pred_logits,  // [256*Q] (NCLS=4)
                    const float4* __restrict__ pred_boxes,   // [256*Q]
                    const float4* __restrict__ tgt_boxes,    // [256*Q]
                    const int4*   __restrict__ hand_type,    // [256*Q/4]
                    float4*       __restrict__ out)          // [256*Q*NVAL/4]
{
    const int gtid = blockIdx.x * 256 + threadIdx.x;   // [0, 32768)
    const int pa = gtid >> 2;                          // i*Q + a
    const int ih = gtid >> 7;                          // sample i
    const int bq = gtid & 3;                           // target quad
    const int ib = (ih << 3) | bq;                     // ids index
    const int tb = (ih << 5) | (bq << 2);              // tgt base

    const float4 p   = __ldg(&pred_boxes [pa]);
    const float4 lg  = __ldg(&pred_logits[pa]);
    const int4   ids = __ldg(&hand_type  [ib]);
    const float4 t0 = __ldg(&tgt_boxes[tb + 0]);
    const float4 t1 = __ldg(&tgt_boxes[tb + 1]);
    const float4 t2 = __ldg(&tgt_boxes[tb + 2]);
    const float4 t3 = __ldg(&tgt_boxes[tb + 3]);

    PredXY pp;
    pp.x0 = p.x - 0.5f * p.z;  pp.y0 = p.y - 0.5f * p.w;
    pp.x1 = p.x + 0.5f * p.z;  pp.y1 = p.y + 0.5f * p.w;
    pp.area = (pp.x1 - pp.x0) * (pp.y1 - pp.y0);

    float4 r;
    r.x = pair_cost(pp, p, t0, sel_logit(lg, ids.x));
    r.y = pair_cost(pp, p, t1, sel_logit(lg, ids.y));
    r.z = pair_cost(pp, p, t2, sel_logit(lg, ids.z));
    r.w = pair_cost(pp, p, t3, sel_logit(lg, ids.w));

    out[gtid] = r;
}

extern "C" void kernel_launch(void* const* d_in, const int* in_sizes, int n_in,
                              void* d_out, int out_size)
{
    const float4* pred_logits = (const float4*)d_in[0];
    const float4* pred_boxes  = (const float4*)d_in[1];
    const float4* tgt_boxes   = (const float4*)d_in[2];
    const int4*   hand_type   = (const int4*)d_in[3];
    (void)in_sizes; (void)n_in; (void)out_size;

    matcher_kernel<<<128, 256>>>(pred_logits, pred_boxes, tgt_boxes,
                                 hand_type, (float4*)d_out);
}